// round 11
// baseline (speedup 1.0000x reference)
#include <cuda_runtime.h>

// ApplyKmeans: tokens[n] = argmin_k ( Cnorm[k] - 2 * dot(x[n], C[:,k]) )
// Output: float32 token values (confirmed R9). Inputs bound by element count.
//
// R11: kernel was smem-crossbar-bound (requested-byte wavefronts), so:
//   * microtile 8x8 per thread (BM=256 x BN=64 per CTA) -> 1.0 B/MAC smem
//     (was 1.5) -> crossbar time x0.67
//   * packed fma.rn.f32x2 over row pairs: A row-pairs load directly as
//     LDS.64 from d-major As; halves FMA issue slots.
// Epilogue (store->barrier->row-owner scan) structure unchanged, widened to
// 256 rows x 8 partials.

#define BM   256      // rows per CTA
#define BN   64       // cluster columns per chunk
#define BK   16       // D-step
#define BMP  260      // BM + 4 pad (260 mod 32 = 4: 2-way store conflicts; float4-aligned)
#define TM   8        // rows per thread (4 packed row-pairs)
#define TN   8        // cols per thread
#define NTH  256      // 32 row-threads x 8 col-threads

static constexpr int ND   = 1024;          // feature dim
static constexpr int NK   = 300;           // clusters
static constexpr int KCH  = 5;             // ceil(300/64)
static constexpr int NIT  = ND / BK;       // 64 D-steps per chunk

__device__ __forceinline__ void ffma2(unsigned long long& d,
                                      unsigned long long a,
                                      unsigned long long b) {
    // packed f32x2 FMA: d.lo += a.lo*b.lo ; d.hi += a.hi*b.hi  (Blackwell)
    asm("fma.rn.f32x2 %0, %1, %2, %0;" : "+l"(d) : "l"(a), "l"(b));
}

__device__ __forceinline__ unsigned long long bcast2(float v) {
    unsigned long long r;
    unsigned u = __float_as_uint(v);
    asm("mov.b64 %0, {%1, %1};" : "=l"(r) : "r"(u));
    return r;
}

__global__ __launch_bounds__(NTH, 2)
void kmeans_assign_kernel(const float* __restrict__ X,
                          const float* __restrict__ C,
                          const float* __restrict__ Cn,
                          float* __restrict__ out)
{
    __shared__ float As[2][BK][BMP];   // [buf][d][row]  D-MAJOR (row pairs contiguous)
    __shared__ float Bs[2][BK][BN];    // [buf][d][col]
    __shared__ float pv[BM][9];        // per-row, per-tx partial best value (padded)
    __shared__ int   pi[BM][9];        // per-row, per-tx partial best index  (padded)

    const int tid = threadIdx.x;
    const int tx  = tid & 7;           // column-thread 0..7  (8 cols each)
    const int ty  = tid >> 3;          // row-thread    0..31 (8 rows each)
    const int ty8 = ty * TM;
    const int tx8 = tx * TN;
    const int row0 = blockIdx.x * BM;

    // global->shared A load mapping: 4 quarters, coalesced 64B segments
    const int a_row = tid >> 2;            // 0..63  (quarters at +64,+128,+192)
    const int a_d   = (tid & 3) << 2;      // 0,4,8,12
    // B load mapping: one float4 per thread
    const int b_dr  = tid >> 4;            // 0..15
    const int b_c   = (tid & 15) << 2;     // 0..60

    const float INF = __int_as_float(0x7f800000);

    // Row-owner running best, in registers. Thread tid owns row tid (0..255).
    float bv_reg = INF;
    int   bi_reg = 0;

    const float* xb = X + (size_t)row0 * ND;

    for (int kc = 0; kc < KCH; ++kc) {
        const int kbase = kc * BN;

        // per-thread Cnorm for its 8 columns; +inf for padded columns (k >= 300)
        float cn[TN];
        #pragma unroll
        for (int j = 0; j < TN; ++j) {
            int k = kbase + tx8 + j;
            cn[j] = (k < NK) ? Cn[k] : INF;
        }

        // packed accumulators: acc2[p][j] holds rows (ty8+2p, ty8+2p+1), col j
        unsigned long long acc2[TM / 2][TN];
        #pragma unroll
        for (int p = 0; p < TM / 2; ++p)
            #pragma unroll
            for (int j = 0; j < TN; ++j) acc2[p][j] = 0ull;

        // ---- prologue: load tile 0 into buffer 0 ----
        float4 ra[4];
        #pragma unroll
        for (int q = 0; q < 4; ++q)
            ra[q] = *(const float4*)(xb + (size_t)(a_row + 64 * q) * ND + a_d);
        float4 rb;
        {
            int col = kbase + b_c;     // col % 4 == 0, 300 % 4 == 0 -> safe float4
            rb = (col < NK) ? *(const float4*)(C + (size_t)b_dr * NK + col)
                            : make_float4(0.f, 0.f, 0.f, 0.f);
        }
        #pragma unroll
        for (int q = 0; q < 4; ++q) {
            const int r = a_row + 64 * q;
            As[0][a_d + 0][r] = ra[q].x; As[0][a_d + 1][r] = ra[q].y;
            As[0][a_d + 2][r] = ra[q].z; As[0][a_d + 3][r] = ra[q].w;
        }
        *(float4*)&Bs[0][b_dr][b_c] = rb;

        // ---- main loop over D, one barrier per iteration ----
        for (int it = 0; it < NIT; ++it) {
            __syncthreads();                 // buf[it&1] ready; buf[(it+1)&1] free
            const int  cur = it & 1;
            const bool pre = (it + 1 < NIT);

            if (pre) {                       // prefetch next tile into registers
                const int d0 = (it + 1) * BK;
                #pragma unroll
                for (int q = 0; q < 4; ++q)
                    ra[q] = *(const float4*)(xb + (size_t)(a_row + 64 * q) * ND + d0 + a_d);
                int col = kbase + b_c;
                rb = (col < NK) ? *(const float4*)(C + (size_t)(d0 + b_dr) * NK + col)
                                : make_float4(0.f, 0.f, 0.f, 0.f);
            }

            #pragma unroll
            for (int d = 0; d < BK; ++d) {
                // A: 4x LDS.64 row-pairs (contiguous rows at fixed d, broadcast)
                unsigned long long a01 = *(const unsigned long long*)&As[cur][d][ty8 + 0];
                unsigned long long a23 = *(const unsigned long long*)&As[cur][d][ty8 + 2];
                unsigned long long a45 = *(const unsigned long long*)&As[cur][d][ty8 + 4];
                unsigned long long a67 = *(const unsigned long long*)&As[cur][d][ty8 + 6];
                // B: 2x LDS.128 -> 8 scalars -> duplicate into packed pairs
                float4 b0 = *(const float4*)&Bs[cur][d][tx8];
                float4 b1 = *(const float4*)&Bs[cur][d][tx8 + 4];
                unsigned long long bb[TN] = {
                    bcast2(b0.x), bcast2(b0.y), bcast2(b0.z), bcast2(b0.w),
                    bcast2(b1.x), bcast2(b1.y), bcast2(b1.z), bcast2(b1.w)
                };
                #pragma unroll
                for (int j = 0; j < TN; ++j) {
                    ffma2(acc2[0][j], a01, bb[j]);
                    ffma2(acc2[1][j], a23, bb[j]);
                    ffma2(acc2[2][j], a45, bb[j]);
                    ffma2(acc2[3][j], a67, bb[j]);
                }
            }

            if (pre) {                       // stage next tile into the other buffer
                const int nxt = cur ^ 1;
                #pragma unroll
                for (int q = 0; q < 4; ++q) {
                    const int r = a_row + 64 * q;
                    As[nxt][a_d + 0][r] = ra[q].x; As[nxt][a_d + 1][r] = ra[q].y;
                    As[nxt][a_d + 2][r] = ra[q].z; As[nxt][a_d + 3][r] = ra[q].w;
                }
                *(float4*)&Bs[nxt][b_dr][b_c] = rb;
            }
        }

        // ---- epilogue: partial argmin -> smem -> row-owner scan ----
        #pragma unroll
        for (int p = 0; p < TM / 2; ++p) {
            #pragma unroll
            for (int h = 0; h < 2; ++h) {        // lo half = row ty8+2p, hi = +1
                float v  = INF;
                int  idx = kbase + tx8;
                #pragma unroll
                for (int j = 0; j < TN; ++j) {
                    unsigned long long w = acc2[p][j];
                    unsigned ubits = h ? (unsigned)(w >> 32) : (unsigned)w;
                    float dot = __uint_as_float(ubits);
                    float vj  = cn[j] - 2.0f * dot;
                    if (vj < v) { v = vj; idx = kbase + tx8 + j; }  // strict <: first-min
                }
                const int r = ty8 + 2 * p + h;
                pv[r][tx] = v;
                pi[r][tx] = idx;
            }
        }
        __syncthreads();                   // partials visible; orders last tile reads
                                           // before next chunk's smem writes

        {                                  // thread tid owns row tid (0..255)
            #pragma unroll
            for (int t = 0; t < 8; ++t) {  // ascending t = ascending k: first-min kept
                float v = pv[tid][t];
                if (v < bv_reg) { bv_reg = v; bi_reg = pi[tid][t]; }
            }
        }
        // pv scan reads vs next chunk's pv writes: separated by the next
        // chunk's 64 in-loop barriers. Prologue buf0 writes are disjoint from pv.
    }

    out[row0 + tid] = (float)bi_reg;       // tokens as FLOAT32 values
}

extern "C" void kernel_launch(void* const* d_in, const int* in_sizes, int n_in,
                              void* d_out, int out_size) {
    // Bind inputs BY ELEMENT COUNT — robust to any metadata.txt ordering.
    //   x:     131072*1024 = 134217728  (largest buffer)
    //   C:     1024*300    = 307200
    //   Cnorm: 300
    //   b, t:  1 each (unused)
    const float* x  = nullptr;
    const float* C  = nullptr;
    const float* Cn = nullptr;
    long long x_elems = 0;
    for (int i = 0; i < n_in; ++i) {
        const long long sz = in_sizes[i];
        if (sz > x_elems) { x = (const float*)d_in[i]; x_elems = sz; }
    }
    for (int i = 0; i < n_in; ++i) {
        const long long sz = in_sizes[i];
        if (sz == (long long)307200) C  = (const float*)d_in[i];
        else if (sz == (long long)300) Cn = (const float*)d_in[i];
    }
    // Fallback (should not trigger): positional binding.
    if (!C || !Cn) {
        x  = (const float*)d_in[0]; x_elems = in_sizes[0];
        C  = (const float*)d_in[1];
        Cn = (const float*)d_in[2];
    }

    float* out = (float*)d_out;                   // [131072] float32 token values

    const int n_rows = (int)(x_elems / ND);       // 131072
    dim3 grid(n_rows / BM);                       // 512 CTAs
    kmeans_assign_kernel<<<grid, NTH>>>(x, C, Cn, out);
}

// round 12
// speedup vs baseline: 2.0950x; 2.0950x over previous
#include <cuda_runtime.h>
#include <cstdint>

// ApplyKmeans: tokens[n] = argmin_k ( Cnorm[k] - 2 * dot(x[n], C[:,k]) )
// Output: float32 token values. Inputs bound by element count.
//
// R12: fp32 CUDA-core roofline (64 MAC/cyc/SM => ~2.1ms) is exhausted.
// Three-kernel tensor pipeline:
//   1) transpose C -> Ct[320][1024] (zero-padded) in __device__ scratch
//   2) tf32 mma.sync GEMM: dist_apx[n][k] = Cnorm[k] - 2*(x.c)_tf32 -> scratch
//   3) rescore: per row, approx-min + margin M=16 candidate set, EXACT fp32
//      re-evaluation of candidates (ascending k, strict < = first-occurrence).
// Margin soundness: |tf32(trunc) dot - fp32 dot| <= 2^-9 * sum|x||c| ~ 3.3
// per distance; M >= 2*B guarantees the exact argmin is a candidate.

static constexpr int ND    = 1024;       // feature dim
static constexpr int NK    = 300;        // clusters
static constexpr int NKP   = 320;        // padded clusters (2 x 160 CTA cols)
static constexpr int DSTR  = 304;        // dist row stride
static constexpr long long NROWS = 131072;

__device__ float g_Ct[(size_t)NKP * ND];            // 1.31 MB: Ct[k][d]
__device__ float g_dist[(size_t)NROWS * DSTR];      // 159 MB: approx distances

// ---------------------------------------------------------------- kernel 1
__global__ void transpose_C_kernel(const float* __restrict__ C) {
    int i = blockIdx.x * 256 + threadIdx.x;          // 0 .. 320*1024-1
    if (i >= NKP * ND) return;
    int k = i >> 10;
    int d = i & (ND - 1);
    g_Ct[i] = (k < NK) ? C[d * NK + k] : 0.0f;
}

// ---------------------------------------------------------------- kernel 2
// tf32 mma GEMM. CTA tile 128(M) x 160(N), 8 warps (2m x 4n), warp 64x40.
// BK=16 (two k8 steps), double-buffered smem, pad-20 rows (conflict-free).
#define PB_M   128
#define PB_N   160
#define PB_K   16
#define PB_PAD 20
#define PB_NIT (ND / PB_K)   // 64

__device__ __forceinline__ void mma_tf32(float* d, const uint32_t* a, const uint32_t* b) {
    asm volatile(
        "mma.sync.aligned.m16n8k8.row.col.f32.tf32.tf32.f32 "
        "{%0,%1,%2,%3}, {%4,%5,%6,%7}, {%8,%9}, {%0,%1,%2,%3};"
        : "+f"(d[0]), "+f"(d[1]), "+f"(d[2]), "+f"(d[3])
        : "r"(a[0]), "r"(a[1]), "r"(a[2]), "r"(a[3]), "r"(b[0]), "r"(b[1]));
}

__global__ __launch_bounds__(256)
void dist_tf32_kernel(const float* __restrict__ X,
                      const float* __restrict__ Cn)
{
    __shared__ float As[2][PB_M][PB_PAD];   // [buf][m][d]
    __shared__ float Bs[2][PB_N][PB_PAD];   // [buf][n][d]   (n = cluster col)

    const int tid  = threadIdx.x;
    const int warp = tid >> 5;
    const int lane = tid & 31;
    const int g    = lane >> 2;      // 0..7
    const int t    = lane & 3;       // 0..3
    const int m0   = (warp >> 2) * 64;   // warp m-base (0 or 64)
    const int n0w  = (warp & 3) * 40;    // warp n-base (0,40,80,120)

    const size_t row0 = (size_t)blockIdx.x * PB_M;
    const int    kc0  = blockIdx.y * PB_N;

    const float* xb  = X + row0 * ND;
    const float* ctb = g_Ct + (size_t)kc0 * ND;

    // accumulators: 4 m-frags x 5 n-frags x 4 regs = 80
    float acc[4][5][4];
    #pragma unroll
    for (int i = 0; i < 4; ++i)
        #pragma unroll
        for (int j = 0; j < 5; ++j)
            #pragma unroll
            for (int r = 0; r < 4; ++r) acc[i][j][r] = 0.0f;

    // global load maps
    const int a_row = tid >> 1;              // 0..127
    const int a_dq  = (tid & 1) * 8;         // 0 or 8 (two float4)
    // B: 160 rows x 4 float4 = 640 float4; thread handles idx, idx+256, idx+512

    float4 raA[2], raB[3];
    // ---- prologue: tile 0 ----
    raA[0] = *(const float4*)(xb + (size_t)a_row * ND + a_dq);
    raA[1] = *(const float4*)(xb + (size_t)a_row * ND + a_dq + 4);
    #pragma unroll
    for (int i = 0; i < 3; ++i) {
        int idx = tid + i * 256;
        if (idx < 640) {
            int bn = idx >> 2, bq = (idx & 3) * 4;
            raB[i] = *(const float4*)(ctb + (size_t)bn * ND + bq);
        }
    }
    *(float4*)&As[0][a_row][a_dq]     = raA[0];
    *(float4*)&As[0][a_row][a_dq + 4] = raA[1];
    #pragma unroll
    for (int i = 0; i < 3; ++i) {
        int idx = tid + i * 256;
        if (idx < 640) {
            int bn = idx >> 2, bq = (idx & 3) * 4;
            *(float4*)&Bs[0][bn][bq] = raB[i];
        }
    }

    for (int it = 0; it < PB_NIT; ++it) {
        __syncthreads();
        const int  cur = it & 1;
        const bool pre = (it + 1 < PB_NIT);

        if (pre) {
            const int d0 = (it + 1) * PB_K;
            raA[0] = *(const float4*)(xb + (size_t)a_row * ND + d0 + a_dq);
            raA[1] = *(const float4*)(xb + (size_t)a_row * ND + d0 + a_dq + 4);
            #pragma unroll
            for (int i = 0; i < 3; ++i) {
                int idx = tid + i * 256;
                if (idx < 640) {
                    int bn = idx >> 2, bq = (idx & 3) * 4;
                    raB[i] = *(const float4*)(ctb + (size_t)bn * ND + d0 + bq);
                }
            }
        }

        #pragma unroll
        for (int k8 = 0; k8 < 2; ++k8) {
            const int kb = k8 * 8;
            uint32_t af[4][4];
            #pragma unroll
            for (int i = 0; i < 4; ++i) {
                const int mr = m0 + 16 * i + g;
                af[i][0] = __float_as_uint(As[cur][mr    ][kb + t]);
                af[i][1] = __float_as_uint(As[cur][mr + 8][kb + t]);
                af[i][2] = __float_as_uint(As[cur][mr    ][kb + t + 4]);
                af[i][3] = __float_as_uint(As[cur][mr + 8][kb + t + 4]);
            }
            uint32_t bf[5][2];
            #pragma unroll
            for (int j = 0; j < 5; ++j) {
                const int nr = n0w + 8 * j + g;
                bf[j][0] = __float_as_uint(Bs[cur][nr][kb + t]);
                bf[j][1] = __float_as_uint(Bs[cur][nr][kb + t + 4]);
            }
            #pragma unroll
            for (int i = 0; i < 4; ++i)
                #pragma unroll
                for (int j = 0; j < 5; ++j)
                    mma_tf32(acc[i][j], af[i], bf[j]);
        }

        if (pre) {
            const int nxt = cur ^ 1;
            *(float4*)&As[nxt][a_row][a_dq]     = raA[0];
            *(float4*)&As[nxt][a_row][a_dq + 4] = raA[1];
            #pragma unroll
            for (int i = 0; i < 3; ++i) {
                int idx = tid + i * 256;
                if (idx < 640) {
                    int bn = idx >> 2, bq = (idx & 3) * 4;
                    *(float4*)&Bs[nxt][bn][bq] = raB[i];
                }
            }
        }
    }

    // ---- epilogue: dist = Cn[k] - 2*dot ----
    #pragma unroll
    for (int j = 0; j < 5; ++j) {
        const int k0 = kc0 + n0w + 8 * j + 2 * t;
        const float cn0 = (k0     < NK) ? Cn[k0]     : 0.0f;
        const float cn1 = (k0 + 1 < NK) ? Cn[k0 + 1] : 0.0f;
        #pragma unroll
        for (int i = 0; i < 4; ++i) {
            const size_t r  = row0 + m0 + 16 * i + g;
            if (k0 < NK) {
                g_dist[r * DSTR + k0]       = cn0 - 2.0f * acc[i][j][0];
                g_dist[(r + 8) * DSTR + k0] = cn0 - 2.0f * acc[i][j][2];
            }
            if (k0 + 1 < NK) {
                g_dist[r * DSTR + k0 + 1]       = cn1 - 2.0f * acc[i][j][1];
                g_dist[(r + 8) * DSTR + k0 + 1] = cn1 - 2.0f * acc[i][j][3];
            }
        }
    }
}

// ---------------------------------------------------------------- kernel 3
// One warp per row: approx min over 300, margin candidates, exact fp32 rescore.
__global__ __launch_bounds__(256)
void rescore_kernel(const float* __restrict__ X,
                    const float* __restrict__ Cn,
                    float* __restrict__ out)
{
    __shared__ float sx[8][ND];
    const int tid  = threadIdx.x;
    const int warp = tid >> 5;
    const int lane = tid & 31;
    const size_t r0 = (size_t)blockIdx.x * 8;
    const float INF = __int_as_float(0x7f800000);
    const float MARGIN = 16.0f;

    // cooperative load of 8 x rows (coalesced float4)
    for (int i = tid; i < 8 * (ND / 4); i += 256) {
        int row = i >> 8;            // /256 float4 per row
        int c4  = i & 255;
        ((float4*)sx[row])[c4] = ((const float4*)(X + (r0 + row) * ND))[c4];
    }
    __syncthreads();

    const size_t r = r0 + warp;
    const float* drow = g_dist + r * DSTR;

    float vals[10];
    float minv = INF; int mink = 0;
    #pragma unroll
    for (int c = 0; c < 10; ++c) {
        int k = c * 32 + lane;
        float v = (k < NK) ? drow[k] : INF;
        vals[c] = v;
        if (v < minv) { minv = v; mink = k; }   // ascending k per lane
    }
    #pragma unroll
    for (int off = 16; off; off >>= 1) {
        float ov = __shfl_xor_sync(0xffffffffu, minv, off);
        int   ok = __shfl_xor_sync(0xffffffffu, mink, off);
        if (ov < minv || (ov == minv && ok < mink)) { minv = ov; mink = ok; }
    }
    const float thr = minv + MARGIN;

    float bestv = INF; int bestk = 0;
    #pragma unroll
    for (int c = 0; c < 10; ++c) {
        unsigned m = __ballot_sync(0xffffffffu, vals[c] < thr);
        while (m) {
            int b = __ffs(m) - 1; m &= m - 1;
            int k = c * 32 + b;                       // ascending k overall
            const float* ct = g_Ct + (size_t)k * ND;
            float a = 0.0f;
            for (int d = lane; d < ND; d += 32)
                a = fmaf(sx[warp][d], ct[d], a);
            #pragma unroll
            for (int off = 16; off; off >>= 1)
                a += __shfl_xor_sync(0xffffffffu, a, off);
            float de = Cn[k] - 2.0f * a;              // exact fp32 distance
            if (de < bestv) { bestv = de; bestk = k; }  // strict <: first-min
        }
    }
    if (lane == 0) out[r] = (float)bestk;
}

// ---------------------------------------------------------------- launch
extern "C" void kernel_launch(void* const* d_in, const int* in_sizes, int n_in,
                              void* d_out, int out_size) {
    // Bind inputs BY ELEMENT COUNT (x = largest; C = 307200; Cnorm = 300).
    const float* x  = nullptr;
    const float* C  = nullptr;
    const float* Cn = nullptr;
    long long x_elems = 0;
    for (int i = 0; i < n_in; ++i) {
        const long long sz = in_sizes[i];
        if (sz > x_elems) { x = (const float*)d_in[i]; x_elems = sz; }
    }
    for (int i = 0; i < n_in; ++i) {
        const long long sz = in_sizes[i];
        if (sz == (long long)307200) C  = (const float*)d_in[i];
        else if (sz == (long long)300) Cn = (const float*)d_in[i];
    }
    if (!C || !Cn) {   // fallback, should not trigger
        x  = (const float*)d_in[0]; x_elems = in_sizes[0];
        C  = (const float*)d_in[1];
        Cn = (const float*)d_in[2];
    }

    float* out = (float*)d_out;                 // [131072] float32 token values
    const int n_rows = (int)(x_elems / ND);     // 131072

    // 1) transpose C -> Ct (zero-padded rows 300..319)
    transpose_C_kernel<<<(NKP * ND + 255) / 256, 256>>>(C);

    // 2) tf32 approx distance GEMM
    dim3 gridB(n_rows / PB_M, NKP / PB_N);      // (1024, 2)
    dist_tf32_kernel<<<gridB, 256>>>(x, Cn);

    // 3) exact rescore of margin candidates
    rescore_kernel<<<n_rows / 8, 256>>>(x, Cn, out);
}

// round 13
// speedup vs baseline: 2.3143x; 1.1047x over previous
#include <cuda_runtime.h>
#include <cuda_bf16.h>
#include <cstdint>

// ApplyKmeans: tokens[n] = argmin_k ( Cnorm[k] - 2 * dot(x[n], C[:,k]) )
// Output: float32 token values. Inputs bound by element count.
//
// R13: approx GEMM switched tf32 m16n8k8 -> bf16 m16n8k16 (full-rate tensor
// format, half the MMA instrs, packed-pair fragment LDS). Margin raised to 24
// (bf16 dot error bound ~2.9 => dist error ~5.8, chain bound ~12, 2x safety).
// Rescore remains EXACT fp32 -> final argmin exact.
//
//   1) transpose C -> g_Ct fp32 (rescore) + g_Ctb bf16 (GEMM B operand)
//   2) bf16 mma.sync GEMM -> g_dist[n][k] approx distances
//   3) rescore: approx min + margin-24 candidates, exact fp32, first-min.

static constexpr int ND    = 1024;       // feature dim
static constexpr int NK    = 300;        // clusters
static constexpr int NKP   = 320;        // padded clusters (2 x 160 CTA cols)
static constexpr int DSTR  = 304;        // dist row stride
static constexpr long long NROWS = 131072;

__device__ float          g_Ct [(size_t)NKP * ND];   // fp32  Ct[k][d] (rescore)
__device__ __nv_bfloat16  g_Ctb[(size_t)NKP * ND];   // bf16  Ct[k][d] (GEMM)
__device__ float          g_dist[(size_t)NROWS * DSTR];

// ---------------------------------------------------------------- kernel 1
__global__ void transpose_C_kernel(const float* __restrict__ C) {
    int i = blockIdx.x * 256 + threadIdx.x;          // 0 .. 320*1024-1
    if (i >= NKP * ND) return;
    int k = i >> 10;
    int d = i & (ND - 1);
    float v = (k < NK) ? C[d * NK + k] : 0.0f;
    g_Ct[i]  = v;
    g_Ctb[i] = __float2bfloat16_rn(v);
}

// ---------------------------------------------------------------- kernel 2
// bf16 mma GEMM. CTA tile 128(M) x 160(N), 8 warps (2m x 4n), warp 64x40.
// BK=32 (two k16 steps), double-buffered smem, 40-elem row stride
// (conflict-free packed-pair loads: bank = (20*row + t) mod 32, all distinct).
#define PB_M   128
#define PB_N   160
#define PB_K   32
#define PB_STR 40                  // bf16 elems per smem row (80 bytes)
#define PB_NIT (ND / PB_K)         // 32

__device__ __forceinline__ void mma_bf16(float* d, const uint32_t* a, const uint32_t* b) {
    asm volatile(
        "mma.sync.aligned.m16n8k16.row.col.f32.bf16.bf16.f32 "
        "{%0,%1,%2,%3}, {%4,%5,%6,%7}, {%8,%9}, {%0,%1,%2,%3};"
        : "+f"(d[0]), "+f"(d[1]), "+f"(d[2]), "+f"(d[3])
        : "r"(a[0]), "r"(a[1]), "r"(a[2]), "r"(a[3]), "r"(b[0]), "r"(b[1]));
}

__global__ __launch_bounds__(256)
void dist_bf16_kernel(const float* __restrict__ X,
                      const float* __restrict__ Cn)
{
    __shared__ __nv_bfloat16 As[2][PB_M][PB_STR];   // [buf][m][k]
    __shared__ __nv_bfloat16 Bs[2][PB_N][PB_STR];   // [buf][n][k]

    const int tid  = threadIdx.x;
    const int warp = tid >> 5;
    const int lane = tid & 31;
    const int g    = lane >> 2;      // 0..7
    const int t    = lane & 3;       // 0..3
    const int m0   = (warp >> 2) * 64;   // warp m-base (0 or 64)
    const int n0w  = (warp & 3) * 40;    // warp n-base (0,40,80,120)

    const size_t row0 = (size_t)blockIdx.x * PB_M;
    const int    kc0  = blockIdx.y * PB_N;

    const float*         xb  = X + row0 * ND;
    const __nv_bfloat16* ctb = g_Ctb + (size_t)kc0 * ND;

    float acc[4][5][4];
    #pragma unroll
    for (int i = 0; i < 4; ++i)
        #pragma unroll
        for (int j = 0; j < 5; ++j)
            #pragma unroll
            for (int r = 0; r < 4; ++r) acc[i][j][r] = 0.0f;

    // A load map: thread -> (row, 16-col half). 128 rows x 32 cols, 16 f32/thread.
    const int a_row  = tid >> 1;             // 0..127
    const int a_half = (tid & 1) * 16;       // 0 or 16
    // B load map: 160 rows x 8 uint2 (4 bf16) per row = 1280; 5 per thread.

    __nv_bfloat162 raA[8];      // staged A tile (16 vals as 8 pairs)
    uint2          raB[5];      // staged B tile

    auto loadA = [&](int d0) {
        #pragma unroll
        for (int q = 0; q < 4; ++q) {
            float4 f = *(const float4*)(xb + (size_t)a_row * ND + d0 + a_half + q * 4);
            raA[q * 2 + 0] = __floats2bfloat162_rn(f.x, f.y);
            raA[q * 2 + 1] = __floats2bfloat162_rn(f.z, f.w);
        }
    };
    auto loadB = [&](int d0) {
        #pragma unroll
        for (int i = 0; i < 5; ++i) {
            int idx = tid + i * 256;         // 0..1279
            int bn = idx >> 3, bq = idx & 7;
            raB[i] = *(const uint2*)(ctb + (size_t)bn * ND + d0 + bq * 4);
        }
    };
    auto storeAB = [&](int buf) {
        *(uint4*)&As[buf][a_row][a_half]     = *(const uint4*)&raA[0];
        *(uint4*)&As[buf][a_row][a_half + 8] = *(const uint4*)&raA[4];
        #pragma unroll
        for (int i = 0; i < 5; ++i) {
            int idx = tid + i * 256;
            int bn = idx >> 3, bq = idx & 7;
            *(uint2*)&Bs[buf][bn][bq * 4] = raB[i];
        }
    };

    // ---- prologue ----
    loadA(0); loadB(0); storeAB(0);

    for (int it = 0; it < PB_NIT; ++it) {
        __syncthreads();
        const int  cur = it & 1;
        const bool pre = (it + 1 < PB_NIT);

        if (pre) { const int d0 = (it + 1) * PB_K; loadA(d0); loadB(d0); }

        #pragma unroll
        for (int k16 = 0; k16 < 2; ++k16) {
            const int kb = k16 * 16;
            uint32_t af[4][4];
            #pragma unroll
            for (int i = 0; i < 4; ++i) {
                const int mr = m0 + 16 * i + g;
                af[i][0] = *(const uint32_t*)&As[cur][mr    ][kb + 2 * t];
                af[i][1] = *(const uint32_t*)&As[cur][mr + 8][kb + 2 * t];
                af[i][2] = *(const uint32_t*)&As[cur][mr    ][kb + 2 * t + 8];
                af[i][3] = *(const uint32_t*)&As[cur][mr + 8][kb + 2 * t + 8];
            }
            uint32_t bf[5][2];
            #pragma unroll
            for (int j = 0; j < 5; ++j) {
                const int nr = n0w + 8 * j + g;
                bf[j][0] = *(const uint32_t*)&Bs[cur][nr][kb + 2 * t];
                bf[j][1] = *(const uint32_t*)&Bs[cur][nr][kb + 2 * t + 8];
            }
            #pragma unroll
            for (int i = 0; i < 4; ++i)
                #pragma unroll
                for (int j = 0; j < 5; ++j)
                    mma_bf16(acc[i][j], af[i], bf[j]);
        }

        if (pre) storeAB(cur ^ 1);
    }

    // ---- epilogue: dist = Cn[k] - 2*dot ----
    #pragma unroll
    for (int j = 0; j < 5; ++j) {
        const int k0 = kc0 + n0w + 8 * j + 2 * t;
        const float cn0 = (k0     < NK) ? Cn[k0]     : 0.0f;
        const float cn1 = (k0 + 1 < NK) ? Cn[k0 + 1] : 0.0f;
        #pragma unroll
        for (int i = 0; i < 4; ++i) {
            const size_t r = row0 + m0 + 16 * i + g;
            if (k0 < NK) {
                g_dist[r * DSTR + k0]       = cn0 - 2.0f * acc[i][j][0];
                g_dist[(r + 8) * DSTR + k0] = cn0 - 2.0f * acc[i][j][2];
            }
            if (k0 + 1 < NK) {
                g_dist[r * DSTR + k0 + 1]       = cn1 - 2.0f * acc[i][j][1];
                g_dist[(r + 8) * DSTR + k0 + 1] = cn1 - 2.0f * acc[i][j][3];
            }
        }
    }
}

// ---------------------------------------------------------------- kernel 3
// One warp per row: approx min over 300, margin candidates, exact fp32 rescore.
__global__ __launch_bounds__(256)
void rescore_kernel(const float* __restrict__ X,
                    const float* __restrict__ Cn,
                    float* __restrict__ out)
{
    __shared__ float sx[8][ND];
    const int tid  = threadIdx.x;
    const int warp = tid >> 5;
    const int lane = tid & 31;
    const size_t r0 = (size_t)blockIdx.x * 8;
    const float INF = __int_as_float(0x7f800000);
    const float MARGIN = 24.0f;          // bf16 chain bound ~12, 2x safety

    for (int i = tid; i < 8 * (ND / 4); i += 256) {
        int row = i >> 8;
        int c4  = i & 255;
        ((float4*)sx[row])[c4] = ((const float4*)(X + (r0 + row) * ND))[c4];
    }
    __syncthreads();

    const size_t r = r0 + warp;
    const float* drow = g_dist + r * DSTR;

    float vals[10];
    float minv = INF; int mink = 0;
    #pragma unroll
    for (int c = 0; c < 10; ++c) {
        int k = c * 32 + lane;
        float v = (k < NK) ? drow[k] : INF;
        vals[c] = v;
        if (v < minv) { minv = v; mink = k; }
    }
    #pragma unroll
    for (int off = 16; off; off >>= 1) {
        float ov = __shfl_xor_sync(0xffffffffu, minv, off);
        int   ok = __shfl_xor_sync(0xffffffffu, mink, off);
        if (ov < minv || (ov == minv && ok < mink)) { minv = ov; mink = ok; }
    }
    const float thr = minv + MARGIN;

    float bestv = INF; int bestk = 0;
    #pragma unroll
    for (int c = 0; c < 10; ++c) {
        unsigned m = __ballot_sync(0xffffffffu, vals[c] < thr);
        while (m) {
            int b = __ffs(m) - 1; m &= m - 1;
            int k = c * 32 + b;                       // ascending k overall
            const float* ct = g_Ct + (size_t)k * ND;
            float a = 0.0f;
            for (int d = lane; d < ND; d += 32)
                a = fmaf(sx[warp][d], ct[d], a);
            #pragma unroll
            for (int off = 16; off; off >>= 1)
                a += __shfl_xor_sync(0xffffffffu, a, off);
            float de = Cn[k] - 2.0f * a;              // exact fp32 distance
            if (de < bestv) { bestv = de; bestk = k; }  // strict <: first-min
        }
    }
    if (lane == 0) out[r] = (float)bestk;
}

// ---------------------------------------------------------------- launch
extern "C" void kernel_launch(void* const* d_in, const int* in_sizes, int n_in,
                              void* d_out, int out_size) {
    // Bind inputs BY ELEMENT COUNT (x = largest; C = 307200; Cnorm = 300).
    const float* x  = nullptr;
    const float* C  = nullptr;
    const float* Cn = nullptr;
    long long x_elems = 0;
    for (int i = 0; i < n_in; ++i) {
        const long long sz = in_sizes[i];
        if (sz > x_elems) { x = (const float*)d_in[i]; x_elems = sz; }
    }
    for (int i = 0; i < n_in; ++i) {
        const long long sz = in_sizes[i];
        if (sz == (long long)307200) C  = (const float*)d_in[i];
        else if (sz == (long long)300) Cn = (const float*)d_in[i];
    }
    if (!C || !Cn) {   // fallback, should not trigger
        x  = (const float*)d_in[0]; x_elems = in_sizes[0];
        C  = (const float*)d_in[1];
        Cn = (const float*)d_in[2];
    }

    float* out = (float*)d_out;                 // [131072] float32 token values
    const int n_rows = (int)(x_elems / ND);     // 131072

    transpose_C_kernel<<<(NKP * ND + 255) / 256, 256>>>(C);

    dim3 gridB(n_rows / PB_M, NKP / PB_N);      // (1024, 2)
    dist_bf16_kernel<<<gridB, 256>>>(x, Cn);

    rescore_kernel<<<n_rows / 8, 256>>>(x, Cn, out);
}

// round 15
// speedup vs baseline: 3.5516x; 1.5346x over previous
#include <cuda_runtime.h>
#include <cuda_bf16.h>
#include <cstdint>

// ApplyKmeans: tokens[n] = argmin_k ( Cnorm[k] - 2 * dot(x[n], C[:,k]) )
// Output: float32 token values. Inputs bound by element count.
//
// R15: tcgen05 unavailable (harness targets sm_103 without 'a'). The bf16
// mma.sync GEMM was HMMA-latency-bound at 1 CTA/SM with register staging.
// Fix: pre-convert X->bf16 once, load A and B tiles with cp.async (no staging
// regs), SW128-swizzled smem, __launch_bounds__(256,2) -> 4 warps/SMSP ->
// 80 independent accumulator chains in flight.
// transpose + rescore (margin 24, exact fp32) unchanged from passing R13.

static constexpr int ND    = 1024;
static constexpr int NK    = 300;
static constexpr int NKP   = 320;        // padded clusters
static constexpr int DSTR  = 304;        // dist row stride
static constexpr long long NROWS = 131072;

__device__ __align__(256) float          g_Ct [(size_t)NKP * ND];   // fp32 Ct[k][d]
__device__ __align__(256) __nv_bfloat16  g_Ctb[(size_t)NKP * ND];   // bf16 Ct[k][d]
__device__ __align__(256) __nv_bfloat16  g_Xb [(size_t)NROWS * ND]; // bf16 X
__device__ __align__(256) float          g_dist[(size_t)NROWS * DSTR];

// ---------------------------------------------------------------- helpers
__device__ __forceinline__ uint32_t smem_u32(const void* p) {
    uint32_t a;
    asm("{ .reg .u64 t; cvta.to.shared.u64 t, %1; cvt.u32.u64 %0, t; }"
        : "=r"(a) : "l"(p));
    return a;
}
__device__ __forceinline__ void cp16(uint32_t dst, const void* src) {
    asm volatile("cp.async.cg.shared.global [%0], [%1], 16;"
                 :: "r"(dst), "l"(src) : "memory");
}
#define CP_COMMIT()  asm volatile("cp.async.commit_group;" ::: "memory")
#define CP_WAIT(n)   asm volatile("cp.async.wait_group %0;" :: "n"(n) : "memory")
#define SMEM_SWZ(o)  ((o) ^ (((o) >> 3) & 0x70))

__device__ __forceinline__ void mma_bf16(float* d, const uint32_t* a, const uint32_t* b) {
    asm volatile(
        "mma.sync.aligned.m16n8k16.row.col.f32.bf16.bf16.f32 "
        "{%0,%1,%2,%3}, {%4,%5,%6,%7}, {%8,%9}, {%0,%1,%2,%3};"
        : "+f"(d[0]), "+f"(d[1]), "+f"(d[2]), "+f"(d[3])
        : "r"(a[0]), "r"(a[1]), "r"(a[2]), "r"(a[3]), "r"(b[0]), "r"(b[1]));
}

// ---------------------------------------------------------------- kernel 0
// X (f32) -> g_Xb (bf16), 8 elems/thread, coalesced.
__global__ void convert_x_kernel(const float* __restrict__ X) {
    size_t i = ((size_t)blockIdx.x * 256 + threadIdx.x) * 8;
    float4 f0 = *(const float4*)(X + i);
    float4 f1 = *(const float4*)(X + i + 4);
    __nv_bfloat162 h0 = __floats2bfloat162_rn(f0.x, f0.y);
    __nv_bfloat162 h1 = __floats2bfloat162_rn(f0.z, f0.w);
    __nv_bfloat162 h2 = __floats2bfloat162_rn(f1.x, f1.y);
    __nv_bfloat162 h3 = __floats2bfloat162_rn(f1.z, f1.w);
    uint4 o;
    o.x = *(uint32_t*)&h0; o.y = *(uint32_t*)&h1;
    o.z = *(uint32_t*)&h2; o.w = *(uint32_t*)&h3;
    *(uint4*)(g_Xb + i) = o;
}

// ---------------------------------------------------------------- kernel 1
__global__ void transpose_C_kernel(const float* __restrict__ C) {
    int i = blockIdx.x * 256 + threadIdx.x;
    if (i >= NKP * ND) return;
    int k = i >> 10;
    int d = i & (ND - 1);
    float v = (k < NK) ? C[d * NK + k] : 0.0f;
    g_Ct[i]  = v;
    g_Ctb[i] = __float2bfloat16_rn(v);
}

// ---------------------------------------------------------------- kernel 2
// bf16 mma.sync GEMM, CTA 128(M) x 160(N), 8 warps (2m x 4n), warp 64x40.
// K chunks of 64 bf16 (one SW128 128B row), cp.async double-buffer (2 groups
// in flight), 2 CTAs/SM.
#define CH       16                     // 1024 / 64
#define A_BYTES  (128 * 128)            // 16 KB per buffer
#define B_BYTES  (160 * 128)            // 20 KB per buffer
#define BUF_BYTES (A_BYTES + B_BYTES)   // 36 KB
#define SMEM_TOT (2 * BUF_BYTES)        // 72 KB

__global__ __launch_bounds__(256, 2)
void dist_bf16_kernel(const float* __restrict__ Cn)
{
    extern __shared__ char smem[];
    const uint32_t sb = smem_u32(smem);

    const int tid  = threadIdx.x;
    const int warp = tid >> 5;
    const int lane = tid & 31;
    const int g    = lane >> 2;          // 0..7
    const int t    = lane & 3;           // 0..3
    const int m0   = (warp >> 2) * 64;   // 0 or 64
    const int n0w  = (warp & 3) * 40;    // 0,40,80,120

    const size_t row0 = (size_t)blockIdx.x * 128;
    const int    kc0  = blockIdx.y * 160;

    const __nv_bfloat16* xb = g_Xb  + row0 * ND;
    const __nv_bfloat16* cb = g_Ctb + (size_t)kc0 * ND;

    float acc[4][5][4];
    #pragma unroll
    for (int i = 0; i < 4; ++i)
        #pragma unroll
        for (int j = 0; j < 5; ++j)
            #pragma unroll
            for (int r = 0; r < 4; ++r) acc[i][j][r] = 0.0f;

    auto issue = [&](int c, int buf) {
        const int d0 = c * 64;                         // bf16 col base
        const uint32_t a_base = sb + buf * BUF_BYTES;
        const uint32_t b_base = a_base + A_BYTES;
        #pragma unroll
        for (int q = 0; q < 4; ++q) {                  // A: 1024 chunks / 256 thr
            int idx = tid + q * 256;
            int r = idx >> 3, bo = (idx & 7) * 16;     // bo: byte offset in row
            cp16(a_base + SMEM_SWZ((uint32_t)(r * 128 + bo)),
                 xb + (size_t)r * ND + d0 + (bo >> 1));
        }
        #pragma unroll
        for (int q = 0; q < 5; ++q) {                  // B: 1280 chunks / 256 thr
            int idx = tid + q * 256;
            int r = idx >> 3, bo = (idx & 7) * 16;
            cp16(b_base + SMEM_SWZ((uint32_t)(r * 128 + bo)),
                 cb + (size_t)r * ND + d0 + (bo >> 1));
        }
        CP_COMMIT();
    };

    issue(0, 0);
    issue(1, 1);

    for (int it = 0; it < CH; ++it) {
        const int cur = it & 1;
        if (it + 1 < CH) { CP_WAIT(1); } else { CP_WAIT(0); }   // tile it arrived
        __syncthreads();

        const char* As = smem + cur * BUF_BYTES;
        const char* Bs = As + A_BYTES;

        #pragma unroll
        for (int k16 = 0; k16 < 4; ++k16) {
            const int kb = k16 * 16;                    // bf16 col base in tile
            uint32_t af[4][4];
            #pragma unroll
            for (int i = 0; i < 4; ++i) {
                const int mr = m0 + 16 * i + g;
                af[i][0] = *(const uint32_t*)(As + SMEM_SWZ((uint32_t)(mr * 128 + (kb + 2*t) * 2)));
                af[i][1] = *(const uint32_t*)(As + SMEM_SWZ((uint32_t)((mr + 8) * 128 + (kb + 2*t) * 2)));
                af[i][2] = *(const uint32_t*)(As + SMEM_SWZ((uint32_t)(mr * 128 + (kb + 2*t + 8) * 2)));
                af[i][3] = *(const uint32_t*)(As + SMEM_SWZ((uint32_t)((mr + 8) * 128 + (kb + 2*t + 8) * 2)));
            }
            uint32_t bf[5][2];
            #pragma unroll
            for (int j = 0; j < 5; ++j) {
                const int nr = n0w + 8 * j + g;
                bf[j][0] = *(const uint32_t*)(Bs + SMEM_SWZ((uint32_t)(nr * 128 + (kb + 2*t) * 2)));
                bf[j][1] = *(const uint32_t*)(Bs + SMEM_SWZ((uint32_t)(nr * 128 + (kb + 2*t + 8) * 2)));
            }
            #pragma unroll
            for (int i = 0; i < 4; ++i)
                #pragma unroll
                for (int j = 0; j < 5; ++j)
                    mma_bf16(acc[i][j], af[i], bf[j]);
        }

        __syncthreads();                                // all warps done with cur buf
        if (it + 2 < CH) issue(it + 2, cur);            // refill cur buffer
    }

    // ---- epilogue: dist = Cn[k] - 2*dot (mapping verified in R13) ----
    #pragma unroll
    for (int j = 0; j < 5; ++j) {
        const int k0 = kc0 + n0w + 8 * j + 2 * t;
        const float cn0 = (k0     < NK) ? Cn[k0]     : 0.0f;
        const float cn1 = (k0 + 1 < NK) ? Cn[k0 + 1] : 0.0f;
        #pragma unroll
        for (int i = 0; i < 4; ++i) {
            const size_t r = row0 + m0 + 16 * i + g;
            if (k0 < NK) {
                g_dist[r * DSTR + k0]       = cn0 - 2.0f * acc[i][j][0];
                g_dist[(r + 8) * DSTR + k0] = cn0 - 2.0f * acc[i][j][2];
            }
            if (k0 + 1 < NK) {
                g_dist[r * DSTR + k0 + 1]       = cn1 - 2.0f * acc[i][j][1];
                g_dist[(r + 8) * DSTR + k0 + 1] = cn1 - 2.0f * acc[i][j][3];
            }
        }
    }
}

// ---------------------------------------------------------------- kernel 3
// One warp per row: approx min over 300, margin candidates, exact fp32 rescore.
__global__ __launch_bounds__(256)
void rescore_kernel(const float* __restrict__ X,
                    const float* __restrict__ Cn,
                    float* __restrict__ out)
{
    __shared__ float sx[8][ND];
    const int tid  = threadIdx.x;
    const int warp = tid >> 5;
    const int lane = tid & 31;
    const size_t r0 = (size_t)blockIdx.x * 8;
    const float INF = __int_as_float(0x7f800000);
    const float MARGIN = 24.0f;          // bf16 chain bound ~12, 2x safety

    for (int i = tid; i < 8 * (ND / 4); i += 256) {
        int row = i >> 8;
        int c4  = i & 255;
        ((float4*)sx[row])[c4] = ((const float4*)(X + (r0 + row) * ND))[c4];
    }
    __syncthreads();

    const size_t r = r0 + warp;
    const float* drow = g_dist + r * DSTR;

    float vals[10];
    float minv = INF; int mink = 0;
    #pragma unroll
    for (int c = 0; c < 10; ++c) {
        int k = c * 32 + lane;
        float v = (k < NK) ? drow[k] : INF;
        vals[c] = v;
        if (v < minv) { minv = v; mink = k; }
    }
    #pragma unroll
    for (int off = 16; off; off >>= 1) {
        float ov = __shfl_xor_sync(0xffffffffu, minv, off);
        int   ok = __shfl_xor_sync(0xffffffffu, mink, off);
        if (ov < minv || (ov == minv && ok < mink)) { minv = ov; mink = ok; }
    }
    const float thr = minv + MARGIN;

    float bestv = INF; int bestk = 0;
    #pragma unroll
    for (int c = 0; c < 10; ++c) {
        unsigned m = __ballot_sync(0xffffffffu, vals[c] < thr);
        while (m) {
            int b = __ffs(m) - 1; m &= m - 1;
            int k = c * 32 + b;                       // ascending k overall
            const float* ct = g_Ct + (size_t)k * ND;
            float a = 0.0f;
            for (int d = lane; d < ND; d += 32)
                a = fmaf(sx[warp][d], ct[d], a);
            #pragma unroll
            for (int off = 16; off; off >>= 1)
                a += __shfl_xor_sync(0xffffffffu, a, off);
            float de = Cn[k] - 2.0f * a;              // exact fp32 distance
            if (de < bestv) { bestv = de; bestk = k; }  // strict <: first-min
        }
    }
    if (lane == 0) out[r] = (float)bestk;
}

// ---------------------------------------------------------------- launch
extern "C" void kernel_launch(void* const* d_in, const int* in_sizes, int n_in,
                              void* d_out, int out_size) {
    // Bind inputs BY ELEMENT COUNT (x = largest; C = 307200; Cnorm = 300).
    const float* x  = nullptr;
    const float* C  = nullptr;
    const float* Cn = nullptr;
    long long x_elems = 0;
    for (int i = 0; i < n_in; ++i) {
        const long long sz = in_sizes[i];
        if (sz > x_elems) { x = (const float*)d_in[i]; x_elems = sz; }
    }
    for (int i = 0; i < n_in; ++i) {
        const long long sz = in_sizes[i];
        if (sz == (long long)307200) C  = (const float*)d_in[i];
        else if (sz == (long long)300) Cn = (const float*)d_in[i];
    }
    if (!C || !Cn) {   // fallback, should not trigger
        x  = (const float*)d_in[0]; x_elems = in_sizes[0];
        C  = (const float*)d_in[1];
        Cn = (const float*)d_in[2];
    }

    float* out = (float*)d_out;                 // [131072] float32 token values
    const int n_rows = (int)(x_elems / ND);     // 131072

    convert_x_kernel<<<(unsigned)(x_elems / (256 * 8)), 256>>>(x);
    transpose_C_kernel<<<(NKP * ND + 255) / 256, 256>>>(C);

    cudaFuncSetAttribute(dist_bf16_kernel,
                         cudaFuncAttributeMaxDynamicSharedMemorySize, SMEM_TOT);
    dim3 gridB(n_rows / 128, NKP / 160);        // (1024, 2)
    dist_bf16_kernel<<<gridB, 256, SMEM_TOT>>>(Cn);

    rescore_kernel<<<n_rows / 8, 256>>>(x, Cn, out);
}